// round 15
// baseline (speedup 1.0000x reference)
#include <cuda_runtime.h>
#include <math.h>
#include <stdint.h>

// ---------------- problem constants ----------------
#define T_P 400
#define T_Q 30
#define NB  32
#define NE  300
#define NH  300
#define NF  300
#define NA  30
#define MP  (T_P*NB)   // 12800 rows (t*32+b)
#define MQ  (T_Q*NB)   // 960
#define HP  304        // padded k length for GRU (aligned float4)

// ---------------- scratch layout (floats) ----------------
#define OFF_PSTAR 0L                      // [MP][600]  (p_emb | q_align)
#define OFF_QEMB  7680000L                // [MQ][300]
#define OFF_FFP   7968000L                // [MP][300]
#define OFF_FFQ   11808000L               // [MQ][300]
#define OFF_XP    12096000L               // [MP][1800] (both dirs side by side per row)
#define OFF_H1    35136000L               // [MP][600]
#define OFF_H2    42816000L               // [MP][600]
#define OFF_SE    50496000L               // [MP][600]  (stt | end fused)
#define OFF_FIN   58176000L               // [NB][12000]
#define OFF_WSE   58560000L               // [600][600] concat stt/end weights
#define OFF_BSE   58920000L               // [600] concat bias
#define SCRATCH_TOTAL 58920640L

__device__ float    g_scratch[SCRATCH_TOTAL];
__device__ float    g_H[2][2][NB][NH];    // [buf][dir][b][u] double-buffered hidden
__device__ unsigned g_bar[8 * 32];        // per-group counters, 128B apart

// ---------------- packed f32x2 helpers (FFMA2 path) ----------------
__device__ __forceinline__ unsigned long long fma2(unsigned long long a,
                                                   unsigned long long b,
                                                   unsigned long long c) {
    unsigned long long d;
    asm("fma.rn.f32x2 %0, %1, %2, %3;" : "=l"(d) : "l"(a), "l"(b), "l"(c));
    return d;
}
__device__ __forceinline__ unsigned long long pack2(float lo, float hi) {
    unsigned long long r;
    asm("mov.b64 %0, {%1, %2};" : "=l"(r) : "f"(lo), "f"(hi));
    return r;
}
__device__ __forceinline__ float2 unpack2(unsigned long long v) {
    float2 f;
    asm("mov.b64 {%0, %1}, %2;" : "=f"(f.x), "=f"(f.y) : "l"(v));
    return f;
}

// ---------------- reset (h state + barrier counters) ----------------
__global__ void reset_kernel() {
    int idx = blockIdx.x * blockDim.x + threadIdx.x;
    int tot = 2 * 2 * NB * NH;
    float* h = &g_H[0][0][0][0];
    for (int i = idx; i < tot; i += gridDim.x * blockDim.x) h[i] = 0.0f;
    if (idx < 8 * 32) g_bar[idx] = 0u;
}

// ---------------- embedding gather ----------------
__global__ void gather_kernel(const int* __restrict__ tok,
                              const float* __restrict__ embed,
                              float* __restrict__ dst, int rows, int dstride) {
    long idx = (long)blockIdx.x * blockDim.x + threadIdx.x;
    long tot = (long)rows * NE;
    if (idx >= tot) return;
    int m = (int)(idx / NE), e = (int)(idx % NE);
    dst[(long)m * dstride + e] = embed[(long)tok[m] * NE + e];
}

// ---------------- concat stt/end weights+bias into one [600][600] ----------------
__global__ void concat_se_kernel(const float* __restrict__ ws, const float* __restrict__ bs,
                                 const float* __restrict__ we, const float* __restrict__ be,
                                 float* __restrict__ Wc, float* __restrict__ bc) {
    int idx = blockIdx.x * blockDim.x + threadIdx.x;
    if (idx < 600 * 600) {
        int r = idx / 600, k = idx % 600;
        Wc[idx] = (r < 300) ? ws[r * 600 + k] : we[(r - 300) * 600 + k];
    }
    if (idx < 600) bc[idx] = (idx < 300) ? bs[idx] : be[idx - 300];
}

// ---------------- SGEMM (f32x2, BK=32, register double-buffer) ----------------
// C[M,N] = A[M,K](lda) @ W[N,K]^T + bias, opt relu
#define BM 128
#define BN 128
#define BK 32
__global__ __launch_bounds__(256)
void sgemm_kernel(int M, int N, int K,
                  const float* __restrict__ A, int lda,
                  const float* __restrict__ W,
                  const float* __restrict__ bias,
                  float* __restrict__ C, int ldc, int do_relu) {
    __shared__ float As[BK][BM + 4];
    __shared__ float Bs[BK][BN + 4];
    int tid  = threadIdx.x;
    int trow = tid >> 4;          // 0..15 (M dir)
    int tcol = tid & 15;          // 0..15 (N dir)
    int aRow = tid >> 3;          // 0..31
    int aCol = tid & 7;           // 0..7 (float4 along K)
    int mBase = blockIdx.y * BM;
    int nBase = blockIdx.x * BN;

    unsigned long long accP[4][8];   // pairs over M: (2i, 2i+1) x 8 N
#pragma unroll
    for (int i = 0; i < 4; i++)
#pragma unroll
        for (int j = 0; j < 8; j++) accP[i][j] = 0ULL;

    float4 pa[4], pb[4];
    // prefetch k-tile 0 into registers
#pragma unroll
    for (int r = 0; r < 4; r++) {
        int m = mBase + aRow + r * 32;
        int k = aCol * 4;
        pa[r] = make_float4(0.f, 0.f, 0.f, 0.f);
        if (m < M && k < K) pa[r] = *reinterpret_cast<const float4*>(A + (long)m * lda + k);
        int n = nBase + aRow + r * 32;
        pb[r] = make_float4(0.f, 0.f, 0.f, 0.f);
        if (n < N && k < K) pb[r] = *reinterpret_cast<const float4*>(W + (long)n * K + k);
    }

    for (int k0 = 0; k0 < K; k0 += BK) {
        // commit prefetched registers to smem (transposed)
#pragma unroll
        for (int r = 0; r < 4; r++) {
            As[aCol * 4 + 0][aRow + r * 32] = pa[r].x;
            As[aCol * 4 + 1][aRow + r * 32] = pa[r].y;
            As[aCol * 4 + 2][aRow + r * 32] = pa[r].z;
            As[aCol * 4 + 3][aRow + r * 32] = pa[r].w;
            Bs[aCol * 4 + 0][aRow + r * 32] = pb[r].x;
            Bs[aCol * 4 + 1][aRow + r * 32] = pb[r].y;
            Bs[aCol * 4 + 2][aRow + r * 32] = pb[r].z;
            Bs[aCol * 4 + 3][aRow + r * 32] = pb[r].w;
        }
        __syncthreads();

        // prefetch NEXT k-tile (LDGs in flight while we compute this tile)
        int kn = k0 + BK;
        if (kn < K) {
#pragma unroll
            for (int r = 0; r < 4; r++) {
                int m = mBase + aRow + r * 32;
                int k = kn + aCol * 4;
                pa[r] = make_float4(0.f, 0.f, 0.f, 0.f);
                if (m < M && k < K) pa[r] = *reinterpret_cast<const float4*>(A + (long)m * lda + k);
                int n = nBase + aRow + r * 32;
                pb[r] = make_float4(0.f, 0.f, 0.f, 0.f);
                if (n < N && k < K) pb[r] = *reinterpret_cast<const float4*>(W + (long)n * K + k);
            }
        }

#pragma unroll
        for (int kk = 0; kk < BK; kk++) {
            ulonglong2 rm01 = *reinterpret_cast<const ulonglong2*>(&As[kk][trow * 8]);
            ulonglong2 rm23 = *reinterpret_cast<const ulonglong2*>(&As[kk][trow * 8 + 4]);
            float4 rnA = *reinterpret_cast<const float4*>(&Bs[kk][tcol * 8]);
            float4 rnB = *reinterpret_cast<const float4*>(&Bs[kk][tcol * 8 + 4]);
            unsigned long long rnD[8];
            rnD[0] = pack2(rnA.x, rnA.x); rnD[1] = pack2(rnA.y, rnA.y);
            rnD[2] = pack2(rnA.z, rnA.z); rnD[3] = pack2(rnA.w, rnA.w);
            rnD[4] = pack2(rnB.x, rnB.x); rnD[5] = pack2(rnB.y, rnB.y);
            rnD[6] = pack2(rnB.z, rnB.z); rnD[7] = pack2(rnB.w, rnB.w);
            unsigned long long rmP[4] = { rm01.x, rm01.y, rm23.x, rm23.y };
#pragma unroll
            for (int i = 0; i < 4; i++)
#pragma unroll
                for (int j = 0; j < 8; j++)
                    accP[i][j] = fma2(rmP[i], rnD[j], accP[i][j]);
        }
        __syncthreads();
    }
#pragma unroll
    for (int i2 = 0; i2 < 4; i2++) {
#pragma unroll
        for (int j = 0; j < 8; j++) {
            int n = nBase + tcol * 8 + j;
            if (n >= N) continue;
            float2 v2 = unpack2(accP[i2][j]);
            float bsv = bias[n];
            int m0 = mBase + trow * 8 + 2 * i2;
            float v = v2.x + bsv;
            if (do_relu) v = fmaxf(v, 0.0f);
            if (m0 < M) C[(long)m0 * ldc + n] = v;
            v = v2.y + bsv;
            if (do_relu) v = fmaxf(v, 0.0f);
            if (m0 + 1 < M) C[(long)(m0 + 1) * ldc + n] = v;
        }
    }
}

// ---------------- attention: scores -> softmax -> q_align (warp per (p,b)) ----------------
__global__ void attn_kernel(const float* __restrict__ ffp,
                            const float* __restrict__ ffq,
                            const float* __restrict__ qemb,
                            float* __restrict__ pstar,
                            const float* __restrict__ pmask,
                            const float* __restrict__ qmask) {
    int gw = (blockIdx.x * blockDim.x + threadIdx.x) >> 5;
    int lane = threadIdx.x & 31;
    if (gw >= MP) return;
    int b = gw & 31;
    int m = gw;

    float fp[10];
#pragma unroll
    for (int c = 0; c < 10; c++) {
        int f = lane + 32 * c;
        fp[c] = (f < NF) ? ffp[(long)m * NF + f] : 0.0f;
    }
    float pm = pmask[m];

    float myscore = 0.0f;
    for (int q = 0; q < T_Q; q++) {
        const float* fq = ffq + (long)(q * NB + b) * NF;
        float a = 0.0f;
#pragma unroll
        for (int c = 0; c < 10; c++) {
            int f = lane + 32 * c;
            if (f < NF) a += fp[c] * fq[f];
        }
#pragma unroll
        for (int o = 16; o; o >>= 1) a += __shfl_xor_sync(0xffffffffu, a, o);
        float s = a * pm * qmask[q * NB + b];
        if (lane == q) myscore = s;
    }
    float val = (lane < T_Q) ? myscore : -INFINITY;
    float mx = val;
#pragma unroll
    for (int o = 16; o; o >>= 1) mx = fmaxf(mx, __shfl_xor_sync(0xffffffffu, mx, o));
    float e = (lane < T_Q) ? expf(val - mx) : 0.0f;
    float sum = e;
#pragma unroll
    for (int o = 16; o; o >>= 1) sum += __shfl_xor_sync(0xffffffffu, sum, o);
    float w = e / sum;

    float acc[10];
#pragma unroll
    for (int c = 0; c < 10; c++) acc[c] = 0.0f;
    for (int q = 0; q < T_Q; q++) {
        float wq = __shfl_sync(0xffffffffu, w, q);
        const float* qe = qemb + (long)(q * NB + b) * NE;
#pragma unroll
        for (int c = 0; c < 10; c++) {
            int f = lane + 32 * c;
            if (f < NE) acc[c] += wq * qe[f];
        }
    }
#pragma unroll
    for (int c = 0; c < 10; c++) {
        int f = lane + 32 * c;
        if (f < NE) pstar[(long)m * 600 + 300 + f] = acc[c];
    }
}

// ---------------- persistent bi-GRU layer (round-13 base, tight poll) ----------------
__global__ __launch_bounds__(320)
void gru_kernel(const float* __restrict__ whh,     // [2][900][300] for this layer
                const float* __restrict__ bhh,     // [2][900]
                const float* __restrict__ xp_all,  // [MP][1800]
                float* __restrict__ out) {         // [MP][600]
    extern __shared__ float sm[];
    float* ws   = sm;              // [60][HP] row rr = ul*3 + gate
    float* h_sm = sm + 60 * HP;    // [8][HP]

    int bx  = blockIdx.x;
    int grp = bx / 15, c = bx % 15;
    int dir = grp >> 2, bg = grp & 3;
    int u0  = c * 20;
    int tid = threadIdx.x;
    int wid = tid >> 5, lane = tid & 31;
    int lb = lane & 7, kq = lane >> 3;

    const float* wbase = whh + (long)dir * 900 * 300;
    for (int e = tid; e < 60 * HP; e += 320) {
        int rr = e / HP, k = e % HP;
        int ul = rr / 3, gate = rr % 3;
        int grow = gate * 300 + u0 + ul;
        ws[e] = (k < 300) ? wbase[(long)grow * 300 + k] : 0.0f;
    }
    for (int e = tid; e < 8 * HP; e += 320) {
        if ((e % HP) >= 300) h_sm[e] = 0.0f;
    }

    int ua = u0 + 2 * wid;
    int ub = ua + 1;
    int bglob = bg * 8 + lb;
    const float* bh = bhh + (long)dir * 900;
    float bra = bh[ua], bza = bh[300 + ua], bna = bh[600 + ua];
    float brb = bh[ub], bzb = bh[300 + ub], bnb = bh[600 + ub];

    unsigned* bar = &g_bar[grp * 32];
    const float4* hsrc0 = reinterpret_cast<const float4*>(&g_H[0][dir][bg * 8][0]);
    const float4* hsrc1 = reinterpret_cast<const float4*>(&g_H[1][dir][bg * 8][0]);
    __syncthreads();

    float xpv[6];
    if (kq == 0) {
        int tt0 = dir ? (T_P - 1) : 0;
        const float* xp = xp_all + ((long)tt0 * NB + bglob) * 1800 + dir * 900;
        xpv[0] = xp[ua]; xpv[1] = xp[300 + ua]; xpv[2] = xp[600 + ua];
        xpv[3] = xp[ub]; xpv[4] = xp[300 + ub]; xpv[5] = xp[600 + ub];
    }

    for (int step = 0; step < T_P; step++) {
        int cur = step & 1;
        int tt  = dir ? (T_P - 1 - step) : step;

        // stage h (8x300) coalesced from L2 into padded smem
        {
            const float4* hsrc = cur ? hsrc1 : hsrc0;
            for (int e = tid; e < 600; e += 320) {
                float4 v = __ldcg(hsrc + e);
                int row = e / 75, col = e - row * 75;
                *reinterpret_cast<float4*>(h_sm + row * HP + col * 4) = v;
            }
        }
        __syncthreads();

        ulonglong2 hPP[19];
        {
            const ulonglong2* hrow =
                reinterpret_cast<const ulonglong2*>(h_sm + lb * HP + kq * 76);
#pragma unroll
            for (int i = 0; i < 19; i++) hPP[i] = hrow[i];
        }

        float res[6];
#pragma unroll
        for (int r6 = 0; r6 < 6; r6++) {
            int rr = wid * 6 + r6;
            const ulonglong2* wr =
                reinterpret_cast<const ulonglong2*>(ws + rr * HP + kq * 76);
            unsigned long long a0 = 0ULL, a1 = 0ULL;
#pragma unroll
            for (int i = 0; i < 19; i++) {
                ulonglong2 wv = wr[i];
                a0 = fma2(hPP[i].x, wv.x, a0);
                a1 = fma2(hPP[i].y, wv.y, a1);
            }
            float2 s0 = unpack2(a0), s1 = unpack2(a1);
            float a = (s0.x + s1.x) + (s0.y + s1.y);
            a += __shfl_xor_sync(0xffffffffu, a, 8);
            a += __shfl_xor_sync(0xffffffffu, a, 16);
            res[r6] = a;
        }

        if (kq == 0) {
            float r = 1.0f / (1.0f + expf(-(xpv[0] + res[0] + bra)));
            float z = 1.0f / (1.0f + expf(-(xpv[1] + res[1] + bza)));
            float n = tanhf(xpv[2] + r * (res[2] + bna));
            float hna = (1.0f - z) * n + z * h_sm[lb * HP + ua];
            r = 1.0f / (1.0f + expf(-(xpv[3] + res[3] + brb)));
            z = 1.0f / (1.0f + expf(-(xpv[4] + res[4] + bzb)));
            n = tanhf(xpv[5] + r * (res[5] + bnb));
            float hnb = (1.0f - z) * n + z * h_sm[lb * HP + ub];
            float2 hv = make_float2(hna, hnb);
            __stcg(reinterpret_cast<float2*>(&g_H[cur ^ 1][dir][bglob][ua]), hv);
            *reinterpret_cast<float2*>(
                out + ((long)tt * NB + bglob) * 600 + dir * 300 + ua) = hv;
        }
        __syncthreads();
        if (step == T_P - 1) break;

        // arrive, overlap next-step xp prefetch with the poll, tight spin
        if (tid == 0) {
            __threadfence();
            atomicAdd(bar, 1u);
        }
        if (kq == 0) {
            int tt2 = dir ? (T_P - 2 - step) : (step + 1);
            const float* xp = xp_all + ((long)tt2 * NB + bglob) * 1800 + dir * 900;
            xpv[0] = xp[ua]; xpv[1] = xp[300 + ua]; xpv[2] = xp[600 + ua];
            xpv[3] = xp[ub]; xpv[4] = xp[300 + ub]; xpv[5] = xp[600 + ub];
        }
        if (tid == 0) {
            unsigned target = (unsigned)(step + 1) * 15u;
            unsigned v;
            do {
                asm volatile("ld.global.cg.u32 %0, [%1];" : "=r"(v) : "l"(bar) : "memory");
            } while (v < target);
            __threadfence();
        }
        __syncthreads();
    }
}

// ---------------- span scoring: block per (i, b), fused stt|end layout ----------------
__global__ void span_kernel(const float* __restrict__ se,   // [MP][600]
                            float* __restrict__ fin,
                            const int* __restrict__ p_lens,
                            const float* __restrict__ w_a) {
    int i = blockIdx.x;   // 0..399
    int b = blockIdx.y;   // 0..31
    __shared__ float st[NF];
    __shared__ float wa[NF];
    int tid = threadIdx.x;
    for (int f = tid; f < NF; f += 128) {
        st[f] = se[((long)i * NB + b) * 600 + f];
        wa[f] = w_a[f];
    }
    __syncthreads();
    int wid = tid >> 5, lane = tid & 31;
    int plen = p_lens[b];
    for (int j = wid; j < NA; j += 4) {
        int k = i + j;
        float a = 0.0f;
        if (k < plen) {
            const float* ed = se + ((long)k * NB + b) * 600 + 300;
#pragma unroll
            for (int cc = 0; cc < 10; cc++) {
                int f = lane + 32 * cc;
                if (f < NF) a += fmaxf(st[f] + ed[f], 0.0f) * wa[f];
            }
#pragma unroll
            for (int o = 16; o; o >>= 1) a += __shfl_xor_sync(0xffffffffu, a, o);
        }
        if (lane == 0) fin[(long)b * (T_P * NA) + i * NA + j] = (k < plen) ? a : 0.0f;
    }
}

// ---------------- log_softmax per batch row ----------------
__global__ void lsm_kernel(const float* __restrict__ fin, float* __restrict__ out) {
    int b = blockIdx.x;
    const float* src = fin + (long)b * (T_P * NA);
    float* dst = out + (long)b * (T_P * NA);
    __shared__ float red[256];
    int tid = threadIdx.x;
    float mx = -INFINITY;
    for (int n = tid; n < T_P * NA; n += 256) mx = fmaxf(mx, src[n]);
    red[tid] = mx; __syncthreads();
    for (int s = 128; s; s >>= 1) { if (tid < s) red[tid] = fmaxf(red[tid], red[tid + s]); __syncthreads(); }
    mx = red[0]; __syncthreads();
    float sum = 0.0f;
    for (int n = tid; n < T_P * NA; n += 256) sum += expf(src[n] - mx);
    red[tid] = sum; __syncthreads();
    for (int s = 128; s; s >>= 1) { if (tid < s) red[tid] += red[tid + s]; __syncthreads(); }
    float lse = mx + logf(red[0]);
    for (int n = tid; n < T_P * NA; n += 256) dst[n] = src[n] - lse;
}

// ---------------- driver ----------------
extern "C" void kernel_launch(void* const* d_in, const int* in_sizes, int n_in,
                              void* d_out, int out_size) {
    const int*   p        = (const int*)  d_in[0];
    const int*   q        = (const int*)  d_in[1];
    const float* p_mask   = (const float*)d_in[2];
    const float* q_mask   = (const float*)d_in[3];
    const int*   p_lens   = (const int*)  d_in[4];
    // d_in[5] = q_lens (unused by reference)
    const float* embed    = (const float*)d_in[6];
    const float* w_align  = (const float*)d_in[7];
    const float* b_align  = (const float*)d_in[8];
    const float* gru_w_ih = (const float*)d_in[9];
    const float* gru_w_hh = (const float*)d_in[10];
    const float* gru_b_ih = (const float*)d_in[11];
    const float* gru_b_hh = (const float*)d_in[12];
    const float* w_stt    = (const float*)d_in[13];
    const float* b_stt    = (const float*)d_in[14];
    const float* w_end    = (const float*)d_in[15];
    const float* b_end    = (const float*)d_in[16];
    const float* w_a      = (const float*)d_in[17];
    float* out = (float*)d_out;

    float* S = nullptr;
    cudaGetSymbolAddress((void**)&S, g_scratch);
    float* pstar = S + OFF_PSTAR;
    float* qemb  = S + OFF_QEMB;
    float* ffp   = S + OFF_FFP;
    float* ffq   = S + OFF_FFQ;
    float* xp    = S + OFF_XP;
    float* h1    = S + OFF_H1;
    float* h2    = S + OFF_H2;
    float* se    = S + OFF_SE;
    float* fin   = S + OFF_FIN;
    float* wse   = S + OFF_WSE;
    float* bse   = S + OFF_BSE;

    const int GRU_SMEM = (60 * HP + 8 * HP) * 4;   // 82688 B
    cudaFuncSetAttribute(gru_kernel, cudaFuncAttributeMaxDynamicSharedMemorySize, GRU_SMEM);

    dim3 blk(256);
    auto grid2 = [](int M, int N) { return dim3((N + BN - 1) / BN, (M + BM - 1) / BM); };

    // 1) reset + gathers + stt/end weight concat (independent prep)
    reset_kernel<<<64, 256>>>();
    concat_se_kernel<<<(600 * 600 + 255) / 256, 256>>>(w_stt, b_stt, w_end, b_end, wse, bse);
    gather_kernel<<<(MP * NE + 255) / 256, 256>>>(p, embed, pstar, MP, 600);
    gather_kernel<<<(MQ * NE + 255) / 256, 256>>>(q, embed, qemb, MQ, 300);

    // 2) aligned-attention features
    sgemm_kernel<<<grid2(MP, NF), blk>>>(MP, NF, NE, pstar, 600, w_align, b_align, ffp, NF, 1);
    sgemm_kernel<<<grid2(MQ, NF), blk>>>(MQ, NF, NE, qemb, 300, w_align, b_align, ffq, NF, 1);

    // 3) attention softmax + q_align -> pstar[:,300:600]
    attn_kernel<<<(MP * 32 + 255) / 256, 256>>>(ffp, ffq, qemb, pstar, p_mask, q_mask);

    // 4) layer-0 input projections (both dirs in ONE GEMM, N=1800) + recurrence
    sgemm_kernel<<<grid2(MP, 1800), blk>>>(MP, 1800, 600, pstar, 600,
                                           gru_w_ih, gru_b_ih, xp, 1800, 0);
    gru_kernel<<<120, 320, GRU_SMEM>>>(gru_w_hh, gru_b_hh, xp, h1);

    // 5) layer-1
    reset_kernel<<<64, 256>>>();
    sgemm_kernel<<<grid2(MP, 1800), blk>>>(MP, 1800, 600, h1, 600,
                                           gru_w_ih + 2L * 900 * 600,
                                           gru_b_ih + 1800, xp, 1800, 0);
    gru_kernel<<<120, 320, GRU_SMEM>>>(gru_w_hh + 2L * 900 * 300,
                                       gru_b_hh + 1800, xp, h2);

    // 6) start/end features in ONE GEMM (N=600, fused weights)
    sgemm_kernel<<<grid2(MP, 600), blk>>>(MP, 600, 600, h2, 600, wse, bse, se, 600, 1);

    // 7) span scoring + masked log-softmax
    span_kernel<<<dim3(T_P, NB), 128>>>(se, fin, p_lens, w_a);
    lsm_kernel<<<NB, 256>>>(fin, out);
}

// round 16
// speedup vs baseline: 1.0640x; 1.0640x over previous
#include <cuda_runtime.h>
#include <math.h>
#include <stdint.h>

// ---------------- problem constants ----------------
#define T_P 400
#define T_Q 30
#define NB  32
#define NE  300
#define NH  300
#define NF  300
#define NA  30
#define MP  (T_P*NB)   // 12800 rows (t*32+b)
#define MQ  (T_Q*NB)   // 960
#define MA  (MP+MQ)    // 13760 rows in merged embed buffer
#define HP  304        // padded k length for GRU (aligned float4)

// ---------------- scratch layout (floats) ----------------
#define OFF_BUF   0L                      // [MA][600]: rows<MP = p_emb|q_align, rows>=MP = q_emb|unused
#define OFF_FFALL 8256000L                // [MA][300]
#define OFF_XP    12384000L               // [MP][1800]
#define OFF_H1    35424000L               // [MP][600]
#define OFF_H2    43104000L               // [MP][600]
#define OFF_SE    50784000L               // [MP][600] (stt | end fused)
#define OFF_FIN   58464000L               // [NB][12000]
#define OFF_WSE   58848000L               // [600][600] concat stt/end weights
#define OFF_BSE   59208000L               // [600] concat bias
#define SCRATCH_TOTAL 59208640L

__device__ float    g_scratch[SCRATCH_TOTAL];
__device__ float    g_H[2][2][NB][NH];    // [buf][dir][b][u] double-buffered hidden
__device__ unsigned g_bar[8 * 32];        // per-group flags: g_bar[grp*32 + c], 128B apart per grp

// ---------------- packed f32x2 helpers (FFMA2 path) ----------------
__device__ __forceinline__ unsigned long long fma2(unsigned long long a,
                                                   unsigned long long b,
                                                   unsigned long long c) {
    unsigned long long d;
    asm("fma.rn.f32x2 %0, %1, %2, %3;" : "=l"(d) : "l"(a), "l"(b), "l"(c));
    return d;
}
__device__ __forceinline__ unsigned long long pack2(float lo, float hi) {
    unsigned long long r;
    asm("mov.b64 %0, {%1, %2};" : "=l"(r) : "f"(lo), "f"(hi));
    return r;
}
__device__ __forceinline__ float2 unpack2(unsigned long long v) {
    float2 f;
    asm("mov.b64 {%0, %1}, %2;" : "=f"(f.x), "=f"(f.y) : "l"(v));
    return f;
}

// ---------------- reset (h state + flags) ----------------
__global__ void reset_kernel() {
    int idx = blockIdx.x * blockDim.x + threadIdx.x;
    int tot = 2 * 2 * NB * NH;
    float* h = &g_H[0][0][0][0];
    for (int i = idx; i < tot; i += gridDim.x * blockDim.x) h[i] = 0.0f;
    if (idx < 8 * 32) g_bar[idx] = 0u;
}

// ---------------- merged embedding gather (p rows then q rows) ----------------
__global__ void gather_kernel(const int* __restrict__ ptok,
                              const int* __restrict__ qtok,
                              const float* __restrict__ embed,
                              float* __restrict__ buf) {
    long idx = (long)blockIdx.x * blockDim.x + threadIdx.x;
    long tot = (long)MA * NE;
    if (idx >= tot) return;
    int m = (int)(idx / NE), e = (int)(idx % NE);
    int t = (m < MP) ? ptok[m] : qtok[m - MP];
    buf[(long)m * 600 + e] = embed[(long)t * NE + e];
}

// ---------------- concat stt/end weights+bias into one [600][600] ----------------
__global__ void concat_se_kernel(const float* __restrict__ ws, const float* __restrict__ bs,
                                 const float* __restrict__ we, const float* __restrict__ be,
                                 float* __restrict__ Wc, float* __restrict__ bc) {
    int idx = blockIdx.x * blockDim.x + threadIdx.x;
    if (idx < 600 * 600) {
        int r = idx / 600, k = idx % 600;
        Wc[idx] = (r < 300) ? ws[r * 600 + k] : we[(r - 300) * 600 + k];
    }
    if (idx < 600) bc[idx] = (idx < 300) ? bs[idx] : be[idx - 300];
}

// ---------------- SGEMM (f32x2, BK=32; proven round-14 version) ----------------
// C[M,N] = A[M,K](lda) @ W[N,K]^T + bias, opt relu
#define BM 128
#define BN 128
#define BK 32
__global__ __launch_bounds__(256, 2)
void sgemm_kernel(int M, int N, int K,
                  const float* __restrict__ A, int lda,
                  const float* __restrict__ W,
                  const float* __restrict__ bias,
                  float* __restrict__ C, int ldc, int do_relu) {
    __shared__ float As[BK][BM + 4];
    __shared__ float Bs[BK][BN + 4];
    int tid  = threadIdx.x;
    int trow = tid >> 4;          // 0..15 (M dir)
    int tcol = tid & 15;          // 0..15 (N dir)
    int aRow = tid >> 3;          // 0..31
    int aCol = tid & 7;           // 0..7 (float4 along K)
    int mBase = blockIdx.y * BM;
    int nBase = blockIdx.x * BN;

    unsigned long long accP[4][8];
#pragma unroll
    for (int i = 0; i < 4; i++)
#pragma unroll
        for (int j = 0; j < 8; j++) accP[i][j] = 0ULL;

    for (int k0 = 0; k0 < K; k0 += BK) {
#pragma unroll
        for (int r = 0; r < 4; r++) {
            int m = mBase + aRow + r * 32;
            int k = k0 + aCol * 4;
            float4 v = make_float4(0.f, 0.f, 0.f, 0.f);
            if (m < M && k < K)
                v = *reinterpret_cast<const float4*>(A + (long)m * lda + k);
            As[aCol * 4 + 0][aRow + r * 32] = v.x;
            As[aCol * 4 + 1][aRow + r * 32] = v.y;
            As[aCol * 4 + 2][aRow + r * 32] = v.z;
            As[aCol * 4 + 3][aRow + r * 32] = v.w;
        }
#pragma unroll
        for (int r = 0; r < 4; r++) {
            int n = nBase + aRow + r * 32;
            int k = k0 + aCol * 4;
            float4 v = make_float4(0.f, 0.f, 0.f, 0.f);
            if (n < N && k < K)
                v = *reinterpret_cast<const float4*>(W + (long)n * K + k);
            Bs[aCol * 4 + 0][aRow + r * 32] = v.x;
            Bs[aCol * 4 + 1][aRow + r * 32] = v.y;
            Bs[aCol * 4 + 2][aRow + r * 32] = v.z;
            Bs[aCol * 4 + 3][aRow + r * 32] = v.w;
        }
        __syncthreads();
#pragma unroll
        for (int kk = 0; kk < BK; kk++) {
            ulonglong2 rm01 = *reinterpret_cast<const ulonglong2*>(&As[kk][trow * 8]);
            ulonglong2 rm23 = *reinterpret_cast<const ulonglong2*>(&As[kk][trow * 8 + 4]);
            float4 rnA = *reinterpret_cast<const float4*>(&Bs[kk][tcol * 8]);
            float4 rnB = *reinterpret_cast<const float4*>(&Bs[kk][tcol * 8 + 4]);
            unsigned long long rnD[8];
            rnD[0] = pack2(rnA.x, rnA.x); rnD[1] = pack2(rnA.y, rnA.y);
            rnD[2] = pack2(rnA.z, rnA.z); rnD[3] = pack2(rnA.w, rnA.w);
            rnD[4] = pack2(rnB.x, rnB.x); rnD[5] = pack2(rnB.y, rnB.y);
            rnD[6] = pack2(rnB.z, rnB.z); rnD[7] = pack2(rnB.w, rnB.w);
            unsigned long long rmP[4] = { rm01.x, rm01.y, rm23.x, rm23.y };
#pragma unroll
            for (int i = 0; i < 4; i++)
#pragma unroll
                for (int j = 0; j < 8; j++)
                    accP[i][j] = fma2(rmP[i], rnD[j], accP[i][j]);
        }
        __syncthreads();
    }
#pragma unroll
    for (int i2 = 0; i2 < 4; i2++) {
#pragma unroll
        for (int j = 0; j < 8; j++) {
            int n = nBase + tcol * 8 + j;
            if (n >= N) continue;
            float2 v2 = unpack2(accP[i2][j]);
            float bsv = bias[n];
            int m0 = mBase + trow * 8 + 2 * i2;
            float v = v2.x + bsv;
            if (do_relu) v = fmaxf(v, 0.0f);
            if (m0 < M) C[(long)m0 * ldc + n] = v;
            v = v2.y + bsv;
            if (do_relu) v = fmaxf(v, 0.0f);
            if (m0 + 1 < M) C[(long)(m0 + 1) * ldc + n] = v;
        }
    }
}

// ---------------- attention (merged-buffer indexing) ----------------
__global__ void attn_kernel(const float* __restrict__ ffall,  // [MA][300]
                            const float* __restrict__ buf,    // [MA][600]
                            float* __restrict__ pstar,        // == buf (writes cols 300..599 of p rows)
                            const float* __restrict__ pmask,
                            const float* __restrict__ qmask) {
    int gw = (blockIdx.x * blockDim.x + threadIdx.x) >> 5;
    int lane = threadIdx.x & 31;
    if (gw >= MP) return;
    int b = gw & 31;
    int m = gw;

    float fp[10];
#pragma unroll
    for (int c = 0; c < 10; c++) {
        int f = lane + 32 * c;
        fp[c] = (f < NF) ? ffall[(long)m * NF + f] : 0.0f;
    }
    float pm = pmask[m];

    float myscore = 0.0f;
    for (int q = 0; q < T_Q; q++) {
        const float* fq = ffall + (long)(MP + q * NB + b) * NF;
        float a = 0.0f;
#pragma unroll
        for (int c = 0; c < 10; c++) {
            int f = lane + 32 * c;
            if (f < NF) a += fp[c] * fq[f];
        }
#pragma unroll
        for (int o = 16; o; o >>= 1) a += __shfl_xor_sync(0xffffffffu, a, o);
        float s = a * pm * qmask[q * NB + b];
        if (lane == q) myscore = s;
    }
    float val = (lane < T_Q) ? myscore : -INFINITY;
    float mx = val;
#pragma unroll
    for (int o = 16; o; o >>= 1) mx = fmaxf(mx, __shfl_xor_sync(0xffffffffu, mx, o));
    float e = (lane < T_Q) ? expf(val - mx) : 0.0f;
    float sum = e;
#pragma unroll
    for (int o = 16; o; o >>= 1) sum += __shfl_xor_sync(0xffffffffu, sum, o);
    float w = e / sum;

    float acc[10];
#pragma unroll
    for (int c = 0; c < 10; c++) acc[c] = 0.0f;
    for (int q = 0; q < T_Q; q++) {
        float wq = __shfl_sync(0xffffffffu, w, q);
        const float* qe = buf + (long)(MP + q * NB + b) * 600;
#pragma unroll
        for (int c = 0; c < 10; c++) {
            int f = lane + 32 * c;
            if (f < NE) acc[c] += wq * qe[f];
        }
    }
#pragma unroll
    for (int c = 0; c < 10; c++) {
        int f = lane + 32 * c;
        if (f < NE) pstar[(long)m * 600 + 300 + f] = acc[c];
    }
}

// ---------------- persistent bi-GRU layer (flag barrier, correct fences) ----------------
// 120 CTAs: 8 groups = (dir) x (bgroup of 8 batches), 15 CTAs/group, 20 units/CTA.
// 320 threads = 10 warps; warp w owns 2 complete units (6 gate rows).
// Barrier: each producer lane fences its own h stores -> __syncthreads ->
// leader release-stores its flag -> poll all 15 flags (4x uint4 from one line)
// -> fence -> __syncthreads. xp prefetch overlaps the poll.
__global__ __launch_bounds__(320)
void gru_kernel(const float* __restrict__ whh,     // [2][900][300] for this layer
                const float* __restrict__ bhh,     // [2][900]
                const float* __restrict__ xp_all,  // [MP][1800]
                float* __restrict__ out) {         // [MP][600]
    extern __shared__ float sm[];
    float* ws   = sm;              // [60][HP] row rr = ul*3 + gate
    float* h_sm = sm + 60 * HP;    // [8][HP]

    int bx  = blockIdx.x;
    int grp = bx / 15, c = bx % 15;
    int dir = grp >> 2, bg = grp & 3;
    int u0  = c * 20;
    int tid = threadIdx.x;
    int wid = tid >> 5, lane = tid & 31;
    int lb = lane & 7, kq = lane >> 3;

    const float* wbase = whh + (long)dir * 900 * 300;
    for (int e = tid; e < 60 * HP; e += 320) {
        int rr = e / HP, k = e % HP;
        int ul = rr / 3, gate = rr % 3;
        int grow = gate * 300 + u0 + ul;
        ws[e] = (k < 300) ? wbase[(long)grow * 300 + k] : 0.0f;
    }
    for (int e = tid; e < 8 * HP; e += 320) {
        if ((e % HP) >= 300) h_sm[e] = 0.0f;
    }

    int ua = u0 + 2 * wid;
    int ub = ua + 1;
    int bglob = bg * 8 + lb;
    const float* bh = bhh + (long)dir * 900;
    float bra = bh[ua], bza = bh[300 + ua], bna = bh[600 + ua];
    float brb = bh[ub], bzb = bh[300 + ub], bnb = bh[600 + ub];

    unsigned* flags = &g_bar[grp * 32];
    unsigned* my_flag = flags + c;
    const float4* hsrc0 = reinterpret_cast<const float4*>(&g_H[0][dir][bg * 8][0]);
    const float4* hsrc1 = reinterpret_cast<const float4*>(&g_H[1][dir][bg * 8][0]);
    __syncthreads();

    float xpv[6];
    if (kq == 0) {
        int tt0 = dir ? (T_P - 1) : 0;
        const float* xp = xp_all + ((long)tt0 * NB + bglob) * 1800 + dir * 900;
        xpv[0] = xp[ua]; xpv[1] = xp[300 + ua]; xpv[2] = xp[600 + ua];
        xpv[3] = xp[ub]; xpv[4] = xp[300 + ub]; xpv[5] = xp[600 + ub];
    }

    for (int step = 0; step < T_P; step++) {
        int cur = step & 1;
        int tt  = dir ? (T_P - 1 - step) : step;

        // stage h (8x300) coalesced from L2 into padded smem
        {
            const float4* hsrc = cur ? hsrc1 : hsrc0;
            for (int e = tid; e < 600; e += 320) {
                float4 v = __ldcg(hsrc + e);
                int row = e / 75, col = e - row * 75;
                *reinterpret_cast<float4*>(h_sm + row * HP + col * 4) = v;
            }
        }
        __syncthreads();

        ulonglong2 hPP[19];
        {
            const ulonglong2* hrow =
                reinterpret_cast<const ulonglong2*>(h_sm + lb * HP + kq * 76);
#pragma unroll
            for (int i = 0; i < 19; i++) hPP[i] = hrow[i];
        }

        float res[6];
#pragma unroll
        for (int r6 = 0; r6 < 6; r6++) {
            int rr = wid * 6 + r6;
            const ulonglong2* wr =
                reinterpret_cast<const ulonglong2*>(ws + rr * HP + kq * 76);
            unsigned long long a0 = 0ULL, a1 = 0ULL;
#pragma unroll
            for (int i = 0; i < 19; i++) {
                ulonglong2 wv = wr[i];
                a0 = fma2(hPP[i].x, wv.x, a0);
                a1 = fma2(hPP[i].y, wv.y, a1);
            }
            float2 s0 = unpack2(a0), s1 = unpack2(a1);
            float a = (s0.x + s1.x) + (s0.y + s1.y);
            a += __shfl_xor_sync(0xffffffffu, a, 8);
            a += __shfl_xor_sync(0xffffffffu, a, 16);
            res[r6] = a;
        }

        if (kq == 0) {
            float r = 1.0f / (1.0f + expf(-(xpv[0] + res[0] + bra)));
            float z = 1.0f / (1.0f + expf(-(xpv[1] + res[1] + bza)));
            float n = tanhf(xpv[2] + r * (res[2] + bna));
            float hna = (1.0f - z) * n + z * h_sm[lb * HP + ua];
            r = 1.0f / (1.0f + expf(-(xpv[3] + res[3] + brb)));
            z = 1.0f / (1.0f + expf(-(xpv[4] + res[4] + bzb)));
            n = tanhf(xpv[5] + r * (res[5] + bnb));
            float hnb = (1.0f - z) * n + z * h_sm[lb * HP + ub];
            float2 hv = make_float2(hna, hnb);
            __stcg(reinterpret_cast<float2*>(&g_H[cur ^ 1][dir][bglob][ua]), hv);
            *reinterpret_cast<float2*>(
                out + ((long)tt * NB + bglob) * 600 + dir * 300 + ua) = hv;
            __threadfence();   // each producer orders ITS OWN h stores (race fix)
        }
        __syncthreads();        // all producers' fences complete before signal
        if (step == T_P - 1) break;

        // leader release-stores its flag (ordered after all fences via the bar)
        unsigned target = (unsigned)(step + 1);
        if (tid == 0) {
            asm volatile("st.global.cg.u32 [%0], %1;" :: "l"(my_flag), "r"(target) : "memory");
        }
        // overlap next-step xp prefetch with the poll
        if (kq == 0) {
            int tt2 = dir ? (T_P - 2 - step) : (step + 1);
            const float* xp = xp_all + ((long)tt2 * NB + bglob) * 1800 + dir * 900;
            xpv[0] = xp[ua]; xpv[1] = xp[300 + ua]; xpv[2] = xp[600 + ua];
            xpv[3] = xp[ub]; xpv[4] = xp[300 + ub]; xpv[5] = xp[600 + ub];
        }
        if (tid == 0) {
            const uint4* fl = reinterpret_cast<const uint4*>(flags);
            while (true) {
                uint4 f0, f1, f2, f3;
                asm volatile("ld.global.cg.v4.u32 {%0,%1,%2,%3}, [%4];"
                             : "=r"(f0.x), "=r"(f0.y), "=r"(f0.z), "=r"(f0.w) : "l"(fl) : "memory");
                asm volatile("ld.global.cg.v4.u32 {%0,%1,%2,%3}, [%4];"
                             : "=r"(f1.x), "=r"(f1.y), "=r"(f1.z), "=r"(f1.w) : "l"(fl + 1) : "memory");
                asm volatile("ld.global.cg.v4.u32 {%0,%1,%2,%3}, [%4];"
                             : "=r"(f2.x), "=r"(f2.y), "=r"(f2.z), "=r"(f2.w) : "l"(fl + 2) : "memory");
                asm volatile("ld.global.cg.v4.u32 {%0,%1,%2,%3}, [%4];"
                             : "=r"(f3.x), "=r"(f3.y), "=r"(f3.z), "=r"(f3.w) : "l"(fl + 3) : "memory");
                unsigned mn = f0.x;
                mn = min(mn, f0.y); mn = min(mn, f0.z); mn = min(mn, f0.w);
                mn = min(mn, f1.x); mn = min(mn, f1.y); mn = min(mn, f1.z); mn = min(mn, f1.w);
                mn = min(mn, f2.x); mn = min(mn, f2.y); mn = min(mn, f2.z); mn = min(mn, f2.w);
                mn = min(mn, f3.x); mn = min(mn, f3.y); mn = min(mn, f3.z);
                if (mn >= target) break;
            }
            __threadfence();
        }
        __syncthreads();
    }
}

// ---------------- span scoring: block per (i, b), fused stt|end layout ----------------
__global__ void span_kernel(const float* __restrict__ se,   // [MP][600]
                            float* __restrict__ fin,
                            const int* __restrict__ p_lens,
                            const float* __restrict__ w_a) {
    int i = blockIdx.x;   // 0..399
    int b = blockIdx.y;   // 0..31
    __shared__ float st[NF];
    __shared__ float wa[NF];
    int tid = threadIdx.x;
    for (int f = tid; f < NF; f += 128) {
        st[f] = se[((long)i * NB + b) * 600 + f];
        wa[f] = w_a[f];
    }
    __syncthreads();
    int wid = tid >> 5, lane = tid & 31;
    int plen = p_lens[b];
    for (int j = wid; j < NA; j += 4) {
        int k = i + j;
        float a = 0.0f;
        if (k < plen) {
            const float* ed = se + ((long)k * NB + b) * 600 + 300;
#pragma unroll
            for (int cc = 0; cc < 10; cc++) {
                int f = lane + 32 * cc;
                if (f < NF) a += fmaxf(st[f] + ed[f], 0.0f) * wa[f];
            }
#pragma unroll
            for (int o = 16; o; o >>= 1) a += __shfl_xor_sync(0xffffffffu, a, o);
        }
        if (lane == 0) fin[(long)b * (T_P * NA) + i * NA + j] = (k < plen) ? a : 0.0f;
    }
}

// ---------------- log_softmax per batch row ----------------
__global__ void lsm_kernel(const float* __restrict__ fin, float* __restrict__ out) {
    int b = blockIdx.x;
    const float* src = fin + (long)b * (T_P * NA);
    float* dst = out + (long)b * (T_P * NA);
    __shared__ float red[256];
    int tid = threadIdx.x;
    float mx = -INFINITY;
    for (int n = tid; n < T_P * NA; n += 256) mx = fmaxf(mx, src[n]);
    red[tid] = mx; __syncthreads();
    for (int s = 128; s; s >>= 1) { if (tid < s) red[tid] = fmaxf(red[tid], red[tid + s]); __syncthreads(); }
    mx = red[0]; __syncthreads();
    float sum = 0.0f;
    for (int n = tid; n < T_P * NA; n += 256) sum += expf(src[n] - mx);
    red[tid] = sum; __syncthreads();
    for (int s = 128; s; s >>= 1) { if (tid < s) red[tid] += red[tid + s]; __syncthreads(); }
    float lse = mx + logf(red[0]);
    for (int n = tid; n < T_P * NA; n += 256) dst[n] = src[n] - lse;
}

// ---------------- driver ----------------
extern "C" void kernel_launch(void* const* d_in, const int* in_sizes, int n_in,
                              void* d_out, int out_size) {
    const int*   p        = (const int*)  d_in[0];
    const int*   q        = (const int*)  d_in[1];
    const float* p_mask   = (const float*)d_in[2];
    const float* q_mask   = (const float*)d_in[3];
    const int*   p_lens   = (const int*)  d_in[4];
    // d_in[5] = q_lens (unused by reference)
    const float* embed    = (const float*)d_in[6];
    const float* w_align  = (const float*)d_in[7];
    const float* b_align  = (const float*)d_in[8];
    const float* gru_w_ih = (const float*)d_in[9];
    const float* gru_w_hh = (const float*)d_in[10];
    const float* gru_b_ih = (const float*)d_in[11];
    const float* gru_b_hh = (const float*)d_in[12];
    const float* w_stt    = (const float*)d_in[13];
    const float* b_stt    = (const float*)d_in[14];
    const float* w_end    = (const float*)d_in[15];
    const float* b_end    = (const float*)d_in[16];
    const float* w_a      = (const float*)d_in[17];
    float* out = (float*)d_out;

    float* S = nullptr;
    cudaGetSymbolAddress((void**)&S, g_scratch);
    float* buf   = S + OFF_BUF;
    float* ffall = S + OFF_FFALL;
    float* xp    = S + OFF_XP;
    float* h1    = S + OFF_H1;
    float* h2    = S + OFF_H2;
    float* se    = S + OFF_SE;
    float* fin   = S + OFF_FIN;
    float* wse   = S + OFF_WSE;
    float* bse   = S + OFF_BSE;

    const int GRU_SMEM = (60 * HP + 8 * HP) * 4;   // 82688 B
    cudaFuncSetAttribute(gru_kernel, cudaFuncAttributeMaxDynamicSharedMemorySize, GRU_SMEM);

    dim3 blk(256);
    auto grid2 = [](int M, int N) { return dim3((N + BN - 1) / BN, (M + BM - 1) / BM); };

    // launches 1-6 arranged so ncu (-s 5 -c 1) captures the GRU kernel
    // 1) reset (h + flags)
    reset_kernel<<<64, 256>>>();
    // 2) merged embedding gather (p + q rows into one lda=600 buffer)
    gather_kernel<<<((long)MA * NE + 255) / 256, 256>>>(p, q, embed, buf);
    // 3) aligned-attention features for p AND q in ONE GEMM
    sgemm_kernel<<<grid2(MA, NF), blk>>>(MA, NF, NE, buf, 600, w_align, b_align, ffall, NF, 1);
    // 4) attention softmax + q_align -> buf[:,300:600] (p rows)
    attn_kernel<<<(MP * 32 + 255) / 256, 256>>>(ffall, buf, buf, p_mask, q_mask);
    // 5) layer-0 input projections (both dirs, N=1800)
    sgemm_kernel<<<grid2(MP, 1800), blk>>>(MP, 1800, 600, buf, 600,
                                           gru_w_ih, gru_b_ih, xp, 1800, 0);
    // 6) layer-0 recurrence  <-- profiled launch
    gru_kernel<<<120, 320, GRU_SMEM>>>(gru_w_hh, gru_b_hh, xp, h1);

    // layer-1
    reset_kernel<<<64, 256>>>();
    concat_se_kernel<<<(600 * 600 + 255) / 256, 256>>>(w_stt, b_stt, w_end, b_end, wse, bse);
    sgemm_kernel<<<grid2(MP, 1800), blk>>>(MP, 1800, 600, h1, 600,
                                           gru_w_ih + 2L * 900 * 600,
                                           gru_b_ih + 1800, xp, 1800, 0);
    gru_kernel<<<120, 320, GRU_SMEM>>>(gru_w_hh + 2L * 900 * 300,
                                       gru_b_hh + 1800, xp, h2);

    // start/end features in ONE GEMM (N=600, fused weights)
    sgemm_kernel<<<grid2(MP, 600), blk>>>(MP, 600, 600, h2, 600, wse, bse, se, 600, 1);

    // span scoring + masked log-softmax
    span_kernel<<<dim3(T_P, NB), 128>>>(se, fin, p_lens, w_a);
    lsm_kernel<<<NB, 256>>>(fin, out);
}